// round 17
// baseline (speedup 1.0000x reference)
#include <cuda_runtime.h>
#include <cuda_bf16.h>
#include <math.h>
#include <stdint.h>

// ---------------------------------------------------------------------------
// PatchEmbed fully fused: polar bilinear sampling + merged-conv GEMM in ONE
// kernel. out[m][o2] = sum_k A[m][k] * Wm[o2][k] + bm[o2],
//   m=(b*16+i2)*64+j2, k=dr*48+c*16+da, K=1200 (25 chunks of 48).
// Sampling math slimmed: coords shared across channels, no masks/clamps
// (provably in-bounds: r<112 -> gx,gy in (0,223)), vectorized STS.64.
// Precision: D = Ah*Bh + Ah*Bl + Al*Bh (fp32 acc).
// (Resubmission of round-14 source: previous bench run hit an infra failure.)
// ---------------------------------------------------------------------------

#define B_SZ 32
#define EMB  96
#define NA   1024
#define KTOT 1200

static __device__ __align__(256) __nv_bfloat16 g_Bh[96 * KTOT];
static __device__ __align__(256) __nv_bfloat16 g_Bl[96 * KTOT];
static __device__ float g_bm[96];

__device__ __forceinline__ uint32_t pack_bf2(__nv_bfloat16 a, __nv_bfloat16 b) {
    return (uint32_t)__bfloat16_as_ushort(a) | ((uint32_t)__bfloat16_as_ushort(b) << 16);
}
__device__ __forceinline__ void split_hl(float v, __nv_bfloat16& h, __nv_bfloat16& l) {
    h = __float2bfloat16(v);
    l = __float2bfloat16(v - __bfloat162float(h));
}
__device__ __forceinline__ uint32_t smem_u32(const void* p) {
    uint32_t a;
    asm("{ .reg .u64 t; cvta.to.shared.u64 t, %1; cvt.u32.u64 %0, t; }" : "=r"(a) : "l"(p));
    return a;
}
__device__ __forceinline__ void cp16(uint32_t dst, const void* src) {
    asm volatile("cp.async.cg.shared.global [%0], [%1], 16;" :: "r"(dst), "l"(src) : "memory");
}
template <int N> __device__ __forceinline__ void cp_wait() {
    asm volatile("cp.async.wait_group %0;" :: "n"(N) : "memory");
}
__device__ __forceinline__ void cp_commit() {
    asm volatile("cp.async.commit_group;" ::: "memory");
}
#define LDSM_X4(r0, r1, r2, r3, a) \
    asm volatile("ldmatrix.sync.aligned.m8n8.x4.shared.b16 {%0,%1,%2,%3}, [%4];" \
                 : "=r"(r0), "=r"(r1), "=r"(r2), "=r"(r3) : "r"(a))
#define LDSM_X2(r0, r1, a) \
    asm volatile("ldmatrix.sync.aligned.m8n8.x2.shared.b16 {%0,%1}, [%2];" \
                 : "=r"(r0), "=r"(r1) : "r"(a))
#define MMA_BF16(c, a0, a1, a2, a3, b0, b1) \
    asm volatile("mma.sync.aligned.m16n8k16.row.col.f32.bf16.bf16.f32 " \
                 "{%0,%1,%2,%3}, {%4,%5,%6,%7}, {%8,%9}, {%0,%1,%2,%3};" \
                 : "+f"((c)[0]), "+f"((c)[1]), "+f"((c)[2]), "+f"((c)[3]) \
                 : "r"(a0), "r"(a1), "r"(a2), "r"(a3), "r"(b0), "r"(b1))

// ---------------- prep: merge conv weights, hi/lo split; bias; theta --------
// grid (96, 5): block (o2, slice) computes k in [slice*240, slice*240+240)
__global__ void __launch_bounds__(256) k_prep(
    const float* __restrict__ w1, const float* __restrict__ b1,
    const float* __restrict__ w2, const float* __restrict__ b2,
    float* __restrict__ out, int write_theta) {
    __shared__ float s_w1[96 * 60];
    __shared__ float s_w2[96 * 20];
    const int o2 = blockIdx.x;
    const int slice = blockIdx.y;
    const int tid = threadIdx.x;
    for (int i = tid; i < 96 * 60; i += 256) s_w1[i] = w1[i];
    for (int i = tid; i < 96 * 20; i += 256) s_w2[i] = w2[o2 * (96 * 20) + i];
    __syncthreads();

    const int k = slice * 240 + tid;
    if (tid < 240) {
        int dr = k / 48, rem = k % 48;
        int c = rem >> 4, da = rem & 15;
        int kr = dr / 5, r5 = dr % 5;
        int ka = da >> 2, a4 = da & 3;
        int w2i = kr * 4 + ka;
        int w1i = c * 20 + r5 * 4 + a4;
        float acc = 0.f;
#pragma unroll 8
        for (int o1 = 0; o1 < 96; o1++)
            acc += s_w2[o1 * 20 + w2i] * s_w1[o1 * 60 + w1i];
        __nv_bfloat16 h, l; split_hl(acc, h, l);
        g_Bh[o2 * KTOT + k] = h;
        g_Bl[o2 * KTOT + k] = l;
    }
    if (slice == 0 && tid == 0) {
        float bm = b2[o2];
        for (int o1 = 0; o1 < 96; o1++) {
            float s = 0.f;
            for (int t = 0; t < 20; t++) s += s_w2[o1 * 20 + t];
            bm += s * b1[o1];
        }
        g_bm[o2] = bm;
    }
    if (write_theta && o2 == 0 && slice == 0 && tid >= 224)
        out[(size_t)B_SZ * 1024 * EMB + (tid - 224)] = 1.57079632679489662f;
}

// ---------------- fused sample + GEMM ----------------------------------------
// stage layout (bytes from stage base, row stride 112B = 56 bf16):
//   Ah 0 (64x112) | Al 7168 | Bh 14336 (96x112) | Bl 25088    STG=35840
static constexpr int STG = 35840;
static constexpr int OFF_AL = 7168, OFF_BH = 14336, OFF_BL = 25088;
static constexpr int OFF_COS = 2 * STG;             // 4096 B
static constexpr int OFF_SIN = OFF_COS + 4096;      // 4096 B
static constexpr int OFF_BIAS = OFF_SIN + 4096;     // 384 B
static constexpr int SMEM_MAIN = OFF_BIAS + 384;    // 80,256 B

__global__ void __launch_bounds__(256, 2) k_main(
    const float* __restrict__ x, const float* __restrict__ dist,
    const __nv_bfloat16* __restrict__ Bh, const __nv_bfloat16* __restrict__ Bl,
    const float* __restrict__ bias, float* __restrict__ outp) {
    extern __shared__ char smc[];
    const uint32_t smb = smem_u32(smc);
    float* s_cos = (float*)(smc + OFF_COS);
    float* s_sin = (float*)(smc + OFF_SIN);
    float* s_bias = (float*)(smc + OFF_BIAS);

    const int tid = threadIdx.x, w = tid >> 5, l = tid & 31;
    const int b = blockIdx.x >> 4;
    const int i2 = blockIdx.x & 15;
    const float PI = 3.14159265358979323846f;

    // prologue: sincos table + bias + distortion coeffs
    for (int ia = tid; ia < NA; ia += 256) {
        float phi = 2.0f * PI * (ia + 0.5f) * (1.0f / (float)NA);
        float sv, cv; sincosf(phi, &sv, &cv);
        s_cos[ia] = cv; s_sin[ia] = sv;
    }
    if (tid < 96) s_bias[tid] = bias[tid];
    const float c0 = 0.2f + dist[b * 4 + 0];
    const float c1 = 0.2f + dist[b * 4 + 1];
    const float c2 = 0.2f + dist[b * 4 + 2];
    const float c3 = 0.2f + dist[b * 4 + 3];
    const float tmax = PI * 0.5f, tm2 = tmax * tmax;
    const float ptm = tmax * (c0 + tm2 * (c1 + tm2 * (c2 + tm2 * c3)));
    const float* xb = x + (size_t)b * (3 * 224 * 224);
    __syncthreads();

    // A-stage store addressing: thread owns 4 consecutive ia = tid*4..tid*4+3
    const int ia0 = tid * 4;
    const uint32_t aoff0 = (uint32_t)(ia0 >> 4) * 112 + (uint32_t)(ia0 & 15) * 2;

    // fill stage s with chunk dr: sample A row + cp.async B chunk
    auto fill = [&](int s, int dr) {
        const uint32_t base = smb + s * STG;
        float th = tmax * ((float)(i2 * 25 + dr) + 0.5f) * (1.0f / 400.0f);
        float t2 = th * th;
        float r = th * (c0 + t2 * (c1 + t2 * (c2 + t2 * c3))) / ptm * 112.0f;

        float vals[3][4];
#pragma unroll
        for (int ci = 0; ci < 4; ci++) {
            const int ia = ia0 + ci;
            float xc = r * s_cos[ia], yc = r * s_sin[ia];
            // gx = (yc/112+1)*0.5*223 = yc*(223/224) + 111.5 ; in (0,223) always
            float gx = fmaf(yc, 223.0f / 224.0f, 111.5f);
            float gy = fmaf(xc, 223.0f / 224.0f, 111.5f);
            float fx0 = floorf(gx), fy0 = floorf(gy);
            float wx1 = gx - fx0, wx0 = 1.0f - wx1;
            float wy1 = gy - fy0, wy0 = 1.0f - wy1;
            float w00 = wx0 * wy0, w10 = wx1 * wy0;
            float w01 = wx0 * wy1, w11 = wx1 * wy1;
            const float* p0 = xb + ((int)fy0 * 224 + (int)fx0);
#pragma unroll
            for (int c = 0; c < 3; c++) {
                const float* p = p0 + c * (224 * 224);
                vals[c][ci] = fmaf(w00, p[0], fmaf(w10, p[1],
                              fmaf(w01, p[224], w11 * p[225])));
            }
        }
#pragma unroll
        for (int c = 0; c < 3; c++) {
            uint32_t hu[2], lu[2];
            __nv_bfloat16 h0, l0, h1, l1;
            split_hl(vals[c][0], h0, l0); split_hl(vals[c][1], h1, l1);
            hu[0] = pack_bf2(h0, h1); lu[0] = pack_bf2(l0, l1);
            split_hl(vals[c][2], h0, l0); split_hl(vals[c][3], h1, l1);
            hu[1] = pack_bf2(h0, h1); lu[1] = pack_bf2(l0, l1);
            const uint32_t off = aoff0 + (uint32_t)c * 32;
            *(uint2*)(smc + s * STG + off) = *(uint2*)hu;
            *(uint2*)(smc + s * STG + OFF_AL + off) = *(uint2*)lu;
        }
        // B chunk: 96 rows x 48 elems, hi+lo = 1152 x 16B
        const size_t koff = (size_t)dr * 48;
#pragma unroll
        for (int t = 0; t < 5; t++) {
            int i = tid + t * 256;
            if (i < 1152) {
                int arr = i >= 576;
                int j = i - arr * 576;
                int row = j / 6, col = j % 6;
                const __nv_bfloat16* src = arr ? Bl : Bh;
                cp16(base + (arr ? OFF_BL : OFF_BH) + row * 112 + col * 16,
                     src + (size_t)row * KTOT + koff + col * 8);
            }
        }
        cp_commit();
    };

    const int warp_m = w & 1, warp_n = w >> 1;        // 2 x 4 warps
    const int mbase = warp_m * 32, nbase = warp_n * 24;
    const int t8 = l >> 3, lr = l & 7;
    const int a_r = (t8 & 1) * 8 + lr, a_c = (t8 >> 1) * 16;
    const int b_r = (t8 >> 1) * 8 + lr, b_c = (t8 & 1) * 16;
    const int b2_r = 16 + lr, b2_c = (t8 & 1) * 16;

    float acc[2][3][4];
#pragma unroll
    for (int mf = 0; mf < 2; mf++)
#pragma unroll
        for (int nt = 0; nt < 3; nt++)
#pragma unroll
            for (int i = 0; i < 4; i++) acc[mf][nt][i] = 0.f;

    fill(0, 0);

    for (int dr = 0; dr < 25; dr++) {
        const int q = dr & 1;
        if (dr + 1 < 25) { fill(q ^ 1, dr + 1); cp_wait<1>(); }
        else             { cp_wait<0>(); }
        __syncthreads();

        const uint32_t sA = smb + q * STG;
        const uint32_t aAh = sA + (mbase + a_r) * 112 + a_c;
        const uint32_t aAl = aAh + OFF_AL;
        const uint32_t aBh = sA + OFF_BH + (nbase + b_r) * 112 + b_c;
        const uint32_t aBl = aBh + (OFF_BL - OFF_BH);
        const uint32_t aBh2 = sA + OFF_BH + (nbase + b2_r) * 112 + b2_c;
        const uint32_t aBl2 = aBh2 + (OFF_BL - OFF_BH);

#pragma unroll
        for (int ks = 0; ks < 3; ks++) {
            const int kb = ks * 32;
            uint32_t ah[2][4], al[2][4], bh[3][2], bl[3][2];
            LDSM_X4(ah[0][0], ah[0][1], ah[0][2], ah[0][3], aAh + kb);
            LDSM_X4(ah[1][0], ah[1][1], ah[1][2], ah[1][3], aAh + 16 * 112 + kb);
            LDSM_X4(al[0][0], al[0][1], al[0][2], al[0][3], aAl + kb);
            LDSM_X4(al[1][0], al[1][1], al[1][2], al[1][3], aAl + 16 * 112 + kb);
            LDSM_X4(bh[0][0], bh[0][1], bh[1][0], bh[1][1], aBh + kb);
            LDSM_X2(bh[2][0], bh[2][1], aBh2 + kb);
            LDSM_X4(bl[0][0], bl[0][1], bl[1][0], bl[1][1], aBl + kb);
            LDSM_X2(bl[2][0], bl[2][1], aBl2 + kb);
#pragma unroll
            for (int mf = 0; mf < 2; mf++)
#pragma unroll
                for (int nt = 0; nt < 3; nt++) {
                    MMA_BF16(acc[mf][nt], ah[mf][0], ah[mf][1], ah[mf][2], ah[mf][3],
                             bh[nt][0], bh[nt][1]);
                    MMA_BF16(acc[mf][nt], ah[mf][0], ah[mf][1], ah[mf][2], ah[mf][3],
                             bl[nt][0], bl[nt][1]);
                    MMA_BF16(acc[mf][nt], al[mf][0], al[mf][1], al[mf][2], al[mf][3],
                             bh[nt][0], bh[nt][1]);
                }
        }
        __syncthreads();
    }

    // epilogue: out[b][i2*64+j2][o2]
    const size_t m0 = (size_t)blockIdx.x * 64;
#pragma unroll
    for (int mf = 0; mf < 2; mf++)
#pragma unroll
        for (int half = 0; half < 2; half++) {
            const size_t m = m0 + mbase + mf * 16 + (l >> 2) + half * 8;
            float* dst = outp + m * 96;
#pragma unroll
            for (int nt = 0; nt < 3; nt++) {
                const int n = nbase + nt * 8 + (l & 3) * 2;
                float2 v;
                v.x = acc[mf][nt][half * 2 + 0] + s_bias[n];
                v.y = acc[mf][nt][half * 2 + 1] + s_bias[n + 1];
                *(float2*)(dst + n) = v;
            }
        }
}

extern "C" void kernel_launch(void* const* d_in, const int* in_sizes, int n_in,
                              void* d_out, int out_size) {
    const float* x    = (const float*)d_in[0];
    const float* dist = (const float*)d_in[1];
    const float* w1   = (const float*)d_in[2];
    const float* b1   = (const float*)d_in[3];
    const float* w2   = (const float*)d_in[4];
    const float* b2   = (const float*)d_in[5];
    float* out = (float*)d_out;

    cudaFuncSetAttribute(k_main, cudaFuncAttributeMaxDynamicSharedMemorySize, SMEM_MAIN);

    __nv_bfloat16 *Bh, *Bl;
    float* bm;
    cudaGetSymbolAddress((void**)&Bh, g_Bh);
    cudaGetSymbolAddress((void**)&Bl, g_Bl);
    cudaGetSymbolAddress((void**)&bm, g_bm);

    const int write_theta = (out_size >= B_SZ * 1024 * EMB + B_SZ) ? 1 : 0;
    k_prep<<<dim3(96, 5), 256>>>(w1, b1, w2, b2, out, write_theta);
    k_main<<<512, 256, SMEM_MAIN>>>(x, dist, Bh, Bl, bm, out);
}